// round 2
// baseline (speedup 1.0000x reference)
#include <cuda_runtime.h>
#include <math.h>

#define B_      8
#define N_      1024
#define DIM_    1024
#define HEADS_  16
#define DH_     64
#define MLP_    4096
#define M_      (B_ * N_)              /* 8192 rows */
#define FUSED_N (3 * DIM_ + MLP_)      /* 7168 */

// ---------------- scratch (static device globals; no runtime allocation) ---
__device__ float g_ss[(size_t)M_ * 2 * DIM_];        // 67 MB   emb@W_emb
__device__ float g_xn[(size_t)M_ * DIM_];            // 32 MB   modulated LN(x)
__device__ float g_fused[(size_t)M_ * FUSED_N];      // 224 MB  qkv | mlp_h
__device__ float g_q[(size_t)M_ * DIM_];             // 32 MB   [B,H,N,Dh]
__device__ float g_k[(size_t)M_ * DIM_];
__device__ float g_v[(size_t)M_ * DIM_];
__device__ float g_o[(size_t)M_ * DIM_];             // attn out, [B,N,DIM]
__device__ float g_x1[(size_t)M_ * DIM_];            // first residual

// ---------------------------------------------------------------- GEMM ----
// C[M,Nc] = op(A)[M,K] @ W[K,Nc] + bias (+ res).  BM=BN=128, BK=8,
// 256 threads, 8x8 accum per thread. All dims here are multiples of tiles.
template <bool SILU_A, bool RES>
__global__ __launch_bounds__(256, 2)
void gemm128(const float* __restrict__ A, int lda,
             const float* __restrict__ W, int Nc,
             const float* __restrict__ bias,
             const float* __restrict__ res,
             float* __restrict__ C, int K)
{
    __shared__ float As[8][128];
    __shared__ float Ws[8][128];

    const int tid  = threadIdx.x;
    const int tx   = tid & 15;
    const int ty   = tid >> 4;
    const int arow = tid >> 1;
    const int acol = (tid & 1) << 2;
    const int wrow = tid >> 5;
    const int wcol = (tid & 31) << 2;

    const float* Ap = A + (size_t)(blockIdx.y * 128 + arow) * lda + acol;
    const float* Wp = W + (size_t)wrow * Nc + blockIdx.x * 128 + wcol;

    float acc[8][8];
#pragma unroll
    for (int i = 0; i < 8; i++)
#pragma unroll
        for (int j = 0; j < 8; j++) acc[i][j] = 0.f;

    for (int k0 = 0; k0 < K; k0 += 8) {
        float4 av = *(const float4*)(Ap + k0);
        if (SILU_A) {
            av.x = av.x / (1.f + __expf(-av.x));
            av.y = av.y / (1.f + __expf(-av.y));
            av.z = av.z / (1.f + __expf(-av.z));
            av.w = av.w / (1.f + __expf(-av.w));
        }
        As[acol + 0][arow] = av.x;
        As[acol + 1][arow] = av.y;
        As[acol + 2][arow] = av.z;
        As[acol + 3][arow] = av.w;

        float4 wv = *(const float4*)(Wp + (size_t)k0 * Nc);
        *(float4*)(&Ws[wrow][wcol]) = wv;

        __syncthreads();
#pragma unroll
        for (int kk = 0; kk < 8; kk++) {
            float a[8], b[8];
#pragma unroll
            for (int i = 0; i < 8; i++) a[i] = As[kk][ty * 8 + i];
#pragma unroll
            for (int j = 0; j < 8; j++) b[j] = Ws[kk][tx * 8 + j];
#pragma unroll
            for (int i = 0; i < 8; i++)
#pragma unroll
                for (int j = 0; j < 8; j++) acc[i][j] += a[i] * b[j];
        }
        __syncthreads();
    }

    const int row0 = blockIdx.y * 128 + ty * 8;
    const int col0 = blockIdx.x * 128 + tx * 8;
#pragma unroll
    for (int i = 0; i < 8; i++) {
        size_t off = (size_t)(row0 + i) * Nc + col0;
#pragma unroll
        for (int j = 0; j < 8; j++) {
            float v = acc[i][j] + bias[col0 + j];
            if (RES) v += res[off + j];
            C[off + j] = v;
        }
    }
}

// --------------------------- LN(x) * (1+scale) + shift  (AdaLN modulate) ---
__global__ __launch_bounds__(256)
void ln_mod_kernel(const float* __restrict__ x,
                   const float* __restrict__ g,
                   const float* __restrict__ b)
{
    const int row = blockIdx.x;
    const int tid = threadIdx.x;
    const float* xr  = x + (size_t)row * DIM_;
    const float* ssr = g_ss + (size_t)row * (2 * DIM_);

    float v[4];
    float s = 0.f, sq = 0.f;
#pragma unroll
    for (int i = 0; i < 4; i++) {
        v[i] = xr[tid + i * 256];
        s += v[i];
        sq += v[i] * v[i];
    }
    __shared__ float sh[2][8];
#pragma unroll
    for (int o = 16; o; o >>= 1) {
        s  += __shfl_xor_sync(0xffffffffu, s, o);
        sq += __shfl_xor_sync(0xffffffffu, sq, o);
    }
    if ((tid & 31) == 0) { sh[0][tid >> 5] = s; sh[1][tid >> 5] = sq; }
    __syncthreads();
    if (tid < 32) {
        s  = (tid < 8) ? sh[0][tid] : 0.f;
        sq = (tid < 8) ? sh[1][tid] : 0.f;
#pragma unroll
        for (int o = 4; o; o >>= 1) {
            s  += __shfl_xor_sync(0xffffffffu, s, o);
            sq += __shfl_xor_sync(0xffffffffu, sq, o);
        }
        if (tid == 0) { sh[0][0] = s; sh[1][0] = sq; }
    }
    __syncthreads();
    s = sh[0][0]; sq = sh[1][0];

    const float mean = s * (1.f / DIM_);
    const float var  = sq * (1.f / DIM_) - mean * mean;
    const float rs   = rsqrtf(var + 1e-5f);
#pragma unroll
    for (int i = 0; i < 4; i++) {
        const int idx = tid + i * 256;
        const float xv = (v[i] - mean) * rs * g[idx] + b[idx];
        g_xn[(size_t)row * DIM_ + idx] = xv * (1.f + ssr[idx]) + ssr[DIM_ + idx];
    }
}

// ------------- per-head q/k layernorm + transpose qkv to [B,H,N,Dh] -------
__global__ __launch_bounds__(256)
void qkv_norm_kernel(const float* __restrict__ qg, const float* __restrict__ qb,
                     const float* __restrict__ kg, const float* __restrict__ kb)
{
    const int row = blockIdx.x;          // b*N + n
    const int bb_ = row >> 10;
    const int n   = row & 1023;
    const int tid = threadIdx.x;
    const float* fr = g_fused + (size_t)row * FUSED_N;

    // v: transpose copy
    for (int i = tid; i < DIM_; i += 256) {
        const int h = i >> 6, d = i & 63;
        g_v[(((size_t)(bb_ * HEADS_ + h)) * N_ + n) * DH_ + d] = fr[2 * DIM_ + i];
    }

    const int warp = tid >> 5, lane = tid & 31;
    for (int t = warp; t < 32; t += 8) {
        const int which = t >> 4;        // 0 = q, 1 = k
        const int h = t & 15;
        const float* base = fr + which * DIM_ + h * DH_;
        float e0 = base[lane], e1 = base[lane + 32];
        float s = e0 + e1, sq = e0 * e0 + e1 * e1;
#pragma unroll
        for (int o = 16; o; o >>= 1) {
            s  += __shfl_xor_sync(0xffffffffu, s, o);
            sq += __shfl_xor_sync(0xffffffffu, sq, o);
        }
        const float mean = s * (1.f / 64.f);
        const float var  = sq * (1.f / 64.f) - mean * mean;
        const float rs   = rsqrtf(var + 1e-5f);
        const float* gg = which ? kg : qg;
        const float* bv = which ? kb : qb;
        float* out = (which ? g_k : g_q) + (((size_t)(bb_ * HEADS_ + h)) * N_ + n) * DH_;
        out[lane]      = (e0 - mean) * rs * gg[lane]      + bv[lane];
        out[lane + 32] = (e1 - mean) * rs * gg[lane + 32] + bv[lane + 32];
    }
}

// ----------------------- flash attention: 1 query row / thread ------------
__global__ __launch_bounds__(128)
void attn_kernel()
{
    const int bh = blockIdx.y;                     // b*16 + h
    const int m  = blockIdx.x * 128 + threadIdx.x; // query index

    const float* qp = g_q + ((size_t)bh * N_ + m) * DH_;
    float q[64];
#pragma unroll
    for (int d = 0; d < 64; d++) q[d] = qp[d] * 0.125f;   // 1/sqrt(64)

    float o[64];
#pragma unroll
    for (int d = 0; d < 64; d++) o[d] = 0.f;
    float mi = -1e30f, li = 0.f;

    __shared__ float ks[64][64];
    __shared__ float vs[64][64];

    for (int t = 0; t < N_; t += 64) {
        const float4* kb = (const float4*)(g_k + ((size_t)bh * N_ + t) * DH_);
        const float4* vb = (const float4*)(g_v + ((size_t)bh * N_ + t) * DH_);
        __syncthreads();
#pragma unroll
        for (int i = 0; i < 8; i++) {
            const int idx = threadIdx.x + i * 128;
            ((float4*)ks)[idx] = kb[idx];
            ((float4*)vs)[idx] = vb[idx];
        }
        __syncthreads();

#pragma unroll 1
        for (int j = 0; j < 64; j++) {
            float s = 0.f;
#pragma unroll
            for (int d = 0; d < 64; d++) s += q[d] * ks[j][d];
            const float mn = fmaxf(mi, s);
            const float p  = __expf(s - mn);
            if (mn != mi) {
                const float corr = __expf(mi - mn);
                li *= corr;
#pragma unroll
                for (int d = 0; d < 64; d++) o[d] *= corr;
                mi = mn;
            }
            li += p;
#pragma unroll
            for (int d = 0; d < 64; d++) o[d] += p * vs[j][d];
        }
    }

    const int b = bh >> 4, h = bh & 15;
    const float inv = 1.f / li;
    float* op = g_o + ((size_t)(b * N_ + m)) * DIM_ + h * DH_;
#pragma unroll
    for (int d = 0; d < 64; d++) op[d] = o[d] * inv;
}

// --------------------------------------------------------------------------
extern "C" void kernel_launch(void* const* d_in, const int* in_sizes, int n_in,
                              void* d_out, int out_size)
{
    const float* x       = (const float*)d_in[0];
    const float* emb     = (const float*)d_in[1];
    const float* W_emb   = (const float*)d_in[2];
    const float* b_emb   = (const float*)d_in[3];
    const float* ln_g    = (const float*)d_in[4];
    const float* ln_b    = (const float*)d_in[5];
    const float* W_fused = (const float*)d_in[6];
    const float* b_fused = (const float*)d_in[7];
    const float* qn_g    = (const float*)d_in[8];
    const float* qn_b    = (const float*)d_in[9];
    const float* kn_g    = (const float*)d_in[10];
    const float* kn_b    = (const float*)d_in[11];
    const float* W_ao    = (const float*)d_in[12];
    const float* b_ao    = (const float*)d_in[13];
    const float* W_mlp   = (const float*)d_in[14];
    const float* b_mlp   = (const float*)d_in[15];
    float* out = (float*)d_out;

    float *ss, *xn, *fused, *o, *x1;
    cudaGetSymbolAddress((void**)&ss,    g_ss);
    cudaGetSymbolAddress((void**)&xn,    g_xn);
    cudaGetSymbolAddress((void**)&fused, g_fused);
    cudaGetSymbolAddress((void**)&o,     g_o);
    cudaGetSymbolAddress((void**)&x1,    g_x1);

    // 1. ss = emb @ W_emb + b_emb                     [8192, 2048]  (EMB_DIM == DIM_)
    gemm128<false, false><<<dim3(2048 / 128, M_ / 128), 256>>>(
        emb, DIM_, W_emb, 2 * DIM_, b_emb, nullptr, ss, DIM_);
    // 2. xn = LN(x)*(1+scale)+shift
    ln_mod_kernel<<<M_, 256>>>(x, ln_g, ln_b);
    // 3. fused = xn @ W_fused + b_fused               [8192, 7168]
    gemm128<false, false><<<dim3(FUSED_N / 128, M_ / 128), 256>>>(
        xn, DIM_, W_fused, FUSED_N, b_fused, nullptr, fused, DIM_);
    // 4. per-head q/k layernorm + transpose
    qkv_norm_kernel<<<M_, 256>>>(qn_g, qn_b, kn_g, kn_b);
    // 5. attention
    attn_kernel<<<dim3(N_ / 128, B_ * HEADS_), 128>>>();
    // 6. x1 = x + o @ W_ao + b_ao
    gemm128<false, true><<<dim3(DIM_ / 128, M_ / 128), 256>>>(
        o, DIM_, W_ao, DIM_, b_ao, x, x1, DIM_);
    // 7. out = x1 + silu(mlp_h) @ W_mlp + b_mlp
    gemm128<true, true><<<dim3(DIM_ / 128, M_ / 128), 256>>>(
        fused + 3 * DIM_, FUSED_N, W_mlp, DIM_, b_mlp, x1, out, MLP_);
}